// round 10
// baseline (speedup 1.0000x reference)
#include <cuda_runtime.h>
#include <math.h>

#define HH 256
#define NP 32
#define LL 8192
#define LH 4097           // L/2 + 1
#define M2 4096           // L/2  (packed real-IFFT size)
#define ROW 4098          // padded k_f row stride (keeps rows 16B-aligned)
#define NUNITS 2048       // 256 heads x 8 chunks of 256 pairs

#ifndef PI_D
#define PI_D 3.14159265358979323846
#endif

// scratch: k_f spectrum, one padded row per head (complex)
__device__ float2 g_kf[HH * ROW];

__device__ __forceinline__ float frcp(float x) {
    float r; asm("rcp.approx.f32 %0,%1;" : "=f"(r) : "f"(x)); return r;
}

// y = 2*tan(pi*l/L); double path near the Nyquist pole where float arg error
// is amplified by 1/(pi/2 - x).
__device__ __forceinline__ float y_of(int l) {
    if (l >= LH) l = LH - 1;                 // clamp dummy lanes
    if (l < 3968) return 2.0f * tanf((float)l * (float)(PI_D / (double)LL));
    return (float)(2.0 * tan((PI_D / (double)LL) * (double)l));
}

// ---------------------------------------------------------------------------
// Cauchy evaluation of one node-pair (2 freqs) against one pole table.
// ---------------------------------------------------------------------------
__device__ __forceinline__ void cauchy_pair(const float4 (*shc)[4],
                                            int p, float2* row)
{
    float y[2];
    y[0] = y_of(2 * p);
    y[1] = y_of(2 * p + 1);

    float r00r[2], r00i[2], r01r[2], r01i[2];
    float r10r[2], r10i[2], r11r[2], r11i[2];
#pragma unroll
    for (int f = 0; f < 2; f++) {
        r00r[f] = r00i[f] = r01r[f] = r01i[f] = 0.f;
        r10r[f] = r10i[f] = r11r[f] = r11i[f] = 0.f;
    }

#pragma unroll 4
    for (int n = 0; n < NP; n++) {
        const float4 c0 = shc[n][0];   // b, a2, s00a, s00b
        const float4 c1 = shc[n][1];   // s00c, s00d, s01a, s01b
        const float4 c2 = shc[n][2];   // s01c, s01d, s10a, s10b
        const float4 c3 = shc[n][3];   // s10c, s10d, s11a, s11b

#pragma unroll
        for (int f = 0; f < 2; f++) {
            const float t1 = y[f] - c0.x;                // y - b
            const float t2 = y[f] + c0.x;                // y + b
            const float inv1 = frcp(fmaf(t1, t1, c0.y)); // 1/(t1^2 + a^2)
            const float inv2 = frcp(fmaf(t2, t2, c0.y));
            const float u1 = t1 * inv1;
            const float u2 = t2 * inv2;
            const float Pinv = inv1 + inv2;
            const float Minv = inv2 - inv1;
            const float Pu = u1 + u2;
            const float Mu = u1 - u2;

            r00r[f] = fmaf(c0.z, Pinv, fmaf(c0.w, Mu,   r00r[f]));
            r00i[f] = fmaf(c1.x, Pu,   fmaf(c1.y, Minv, r00i[f]));
            r01r[f] = fmaf(c1.z, Pinv, fmaf(c1.w, Mu,   r01r[f]));
            r01i[f] = fmaf(c2.x, Pu,   fmaf(c2.y, Minv, r01i[f]));
            r10r[f] = fmaf(c2.z, Pinv, fmaf(c2.w, Mu,   r10r[f]));
            r10i[f] = fmaf(c3.x, Pu,   fmaf(c3.y, Minv, r10i[f]));
            r11r[f] = fmaf(c3.z, Pinv, r11r[f]);
            r11i[f] = fmaf(c3.w, Pu,   r11i[f]);
        }
    }

    // Woodbury: k_f = (r00 - r01*r10/(1+r11)) * (1 + i*y/2)   (dt already in)
    float2 res[2];
#pragma unroll
    for (int s = 0; s < 2; s++) {
        const float drw = 1.f + r11r[s], diw = r11i[s];
        const float invd = frcp(fmaf(drw, drw, diw * diw));
        const float numr = r01r[s] * r10r[s] - r01i[s] * r10i[s];
        const float numi = r01r[s] * r10i[s] + r01i[s] * r10r[s];
        const float cr = (numr * drw + numi * diw) * invd;
        const float ci = (numi * drw - numr * diw) * invd;
        const float ar = r00r[s] - cr, ai = r00i[s] - ci;
        const float g = 0.5f * y[s];
        res[s] = make_float2(fmaf(-ai, g, ar), fmaf(ar, g, ai));
    }

    if (p < 2048) {
        *reinterpret_cast<float4*>(row + 2 * p) =
            make_float4(res[0].x, res[0].y, res[1].x, res[1].y);
    } else {
        row[2 * p] = res[0];                  // l = 4096 tail, single freq
    }
}

// ---------------------------------------------------------------------------
// Kernel A: persistent grid. Unit u = (head u>>3, chunk u&7); a unit is 256
// node-pairs computed by 256 threads (1 pair each). Thread 0 of chunk 0 also
// does the l=4096 tail pair. Head constants double-buffered in shared ->
// one __syncthreads per unit.
// ---------------------------------------------------------------------------
__global__ __launch_bounds__(256) void cauchy_kernel(
    const float* __restrict__ w_re, const float* __restrict__ w_im,
    const float* __restrict__ p_re, const float* __restrict__ p_im,
    const float* __restrict__ B_re, const float* __restrict__ B_im,
    const float* __restrict__ C_re, const float* __restrict__ C_im,
    const float* __restrict__ log_dt)
{
    __shared__ float4 sh[2][NP][4];

    const int tid = threadIdx.x;
    int buf = 0;

    for (int u = blockIdx.x; u < NUNITS; u += gridDim.x, buf ^= 1) {
        const int h = u >> 3;
        const int c = u & 7;

        if (tid < NP) {
            const float dt = expf(log_dt[h]);
            const int idx = h * NP + tid;
            const float a  = w_re[idx] * dt;      // fold dt into pole
            const float b  = w_im[idx] * dt;
            const float Br = B_re[idx], Bi = B_im[idx];
            const float Pr = p_re[idx], Pi = p_im[idx];
            const float Cr = C_re[idx], Ci = C_im[idx];
            const float v00r = (Br * Cr - Bi * Ci) * dt, v00i = (Br * Ci + Bi * Cr) * dt;
            const float v01r = (Br * Pr + Bi * Pi) * dt, v01i = (Bi * Pr - Br * Pi) * dt;
            const float v10r = (Pr * Cr - Pi * Ci) * dt, v10i = (Pr * Ci + Pi * Cr) * dt;
            const float v11  = (Pr * Pr + Pi * Pi) * dt;
            sh[buf][tid][0] = make_float4(b, a * a, -a * v00r, v00i);
            sh[buf][tid][1] = make_float4(-v00r, a * v00i, -a * v01r, v01i);
            sh[buf][tid][2] = make_float4(-v01r, a * v01i, -a * v10r, v10i);
            sh[buf][tid][3] = make_float4(-v10r, a * v10i, -a * v11, -v11);
        }
        __syncthreads();     // sh[buf] ready; also fences compute from u-2 on this buf

        float2* row = g_kf + h * ROW;
        cauchy_pair(sh[buf], c * 256 + tid, row);
        if (c == 0 && tid == 0) {
            cauchy_pair(sh[buf], 2048, row);   // l = 4096 tail
        }
    }
}

// ---------------------------------------------------------------------------
// FFT helpers
// ---------------------------------------------------------------------------
__device__ __forceinline__ float2 cmul(float2 a, float2 b) {
    return make_float2(a.x * b.x - a.y * b.y, a.x * b.y + a.y * b.x);
}
__device__ __forceinline__ float2 cadd(float2 a, float2 b) {
    return make_float2(a.x + b.x, a.y + b.y);
}
__device__ __forceinline__ float2 csub(float2 a, float2 b) {
    return make_float2(a.x - b.x, a.y - b.y);
}
__device__ __forceinline__ float2 cmuli(float2 a) {     // i*a
    return make_float2(-a.y, a.x);
}
__device__ __forceinline__ int rev8(int k) {  // base-8 digit reversal, 12-bit
    return ((k & 7) << 9) | (((k >> 3) & 7) << 6) | (((k >> 6) & 7) << 3) | ((k >> 9) & 7);
}
#define PAD(i) ((i) + ((i) >> 3))             // smem skew: 4096 -> 4608 slots

// ---------------------------------------------------------------------------
// Kernel B: irfft(k_f), ONE head per 512-thread block, radix-8 DIT
// (4 stages, 3 barriers), last stage writes gmem from registers.
// grid = 256, block = 512, 36 KB dynamic shared (under 48 KB default).
// ---------------------------------------------------------------------------
__global__ __launch_bounds__(512) void ifft_kernel(float* __restrict__ out)
{
    extern __shared__ float2 spec[];          // 4608 float2 (36 KB)

    const int stid = threadIdx.x;             // 0..511
    const int h    = blockIdx.x;

    // Hermitian pack with 1/M scale folded in, base-8 digit-reversed layout.
    const float sc = 0.5f / (float)M2;
    const float2* kf = g_kf + h * ROW;
    for (int k = stid; k <= M2 / 2; k += 512) {
        const float2 Xk = kf[k];
        const float2 Xm = kf[M2 - k];
        const float mr = Xm.x, mi = -Xm.y;            // conj(X[M-k])
        const float Er = sc * (Xk.x + mr);
        const float Ei = sc * (Xk.y + mi);
        const float Fr = sc * (Xk.x - mr);
        const float Fi = sc * (Xk.y - mi);
        float s, c;
        __sincosf((float)k * (float)(PI_D / (double)M2), &s, &c); // e^{+i*pi*k/M}
        const float Or = c * Fr - s * Fi;
        const float Oi = c * Fi + s * Fr;
        spec[PAD(rev8(k))] = make_float2(Er - Oi, Ei + Or);
        if (k > 0 && k < M2 / 2) {
            spec[PAD(rev8(M2 - k))] = make_float2(Er + Oi, Or - Ei);
        }
    }
    __syncthreads();

    const float C8 = 0.70710678118654752f;    // sqrt(2)/2
    float2* outv = (float2*)out + h * M2;

    // 4 radix-8 stages: q = 1, 8, 64, 512. 512 butterflies/stage, 1/thread.
#pragma unroll 1
    for (int st = 0; st < 4; st++) {
        const int lq = 3 * st;                // log8 shift
        const int q  = 1 << lq;
        const int j  = stid;
        const int pos = j & (q - 1);
        const int i0  = ((j >> lq) << (lq + 3)) | pos;

        float2 v[8];
#pragma unroll
        for (int m = 0; m < 8; m++) v[m] = spec[PAD(i0 + m * q)];

        if (st > 0) {
            // external twiddles: v[m] *= e^{+2*pi*i*m*pos/(8q)}
            float s1, c1;
            __sincosf((float)pos * (float)(2.0 * PI_D / (8.0 * (double)q)), &s1, &c1);
            const float2 w1 = make_float2(c1, s1);
            const float2 w2 = cmul(w1, w1);
            const float2 w3 = cmul(w2, w1);
            const float2 w4 = cmul(w2, w2);
            const float2 w5 = cmul(w2, w3);
            const float2 w6 = cmul(w3, w3);
            const float2 w7 = cmul(w3, w4);
            v[1] = cmul(v[1], w1); v[2] = cmul(v[2], w2); v[3] = cmul(v[3], w3);
            v[4] = cmul(v[4], w4); v[5] = cmul(v[5], w5); v[6] = cmul(v[6], w6);
            v[7] = cmul(v[7], w7);
        }

        // inverse DFT8: even DFT4 (v0,v2,v4,v6), odd DFT4 (v1,v3,v5,v7), combine
        const float2 es = cadd(v[0], v[4]), ed = csub(v[0], v[4]);
        const float2 fs = cadd(v[2], v[6]), fd = csub(v[2], v[6]);
        const float2 E0 = cadd(es, fs);
        const float2 E1 = cadd(ed, cmuli(fd));
        const float2 E2 = csub(es, fs);
        const float2 E3 = csub(ed, cmuli(fd));

        const float2 os = cadd(v[1], v[5]), od = csub(v[1], v[5]);
        const float2 ps = cadd(v[3], v[7]), pd = csub(v[3], v[7]);
        const float2 O0 = cadd(os, ps);
        const float2 O1 = cadd(od, cmuli(pd));
        const float2 O2 = csub(os, ps);
        const float2 O3 = csub(od, cmuli(pd));

        // W8^m * O[m]:  W8^1=c(1+i), W8^2=i, W8^3=c(-1+i)
        const float2 T1 = make_float2(C8 * (O1.x - O1.y), C8 * (O1.x + O1.y));
        const float2 T2 = cmuli(O2);
        const float2 T3 = make_float2(C8 * (-O3.x - O3.y), C8 * (O3.x - O3.y));

        float2 X[8];
        X[0] = cadd(E0, O0);  X[4] = csub(E0, O0);
        X[1] = cadd(E1, T1);  X[5] = csub(E1, T1);
        X[2] = cadd(E2, T2);  X[6] = csub(E2, T2);
        X[3] = cadd(E3, T3);  X[7] = csub(E3, T3);

        if (st < 3) {
#pragma unroll
            for (int m = 0; m < 8; m++) spec[PAD(i0 + m * q)] = X[m];
            __syncthreads();
        } else {
            // q = 512, i0 = j: z[t] = x[2t] + i*x[2t+1], already scaled.
#pragma unroll
            for (int m = 0; m < 8; m++) outv[i0 + m * 512] = X[m];
        }
    }
}

// ---------------------------------------------------------------------------
extern "C" void kernel_launch(void* const* d_in, const int* in_sizes, int n_in,
                              void* d_out, int out_size)
{
    const float* w_re   = (const float*)d_in[0];
    const float* w_im   = (const float*)d_in[1];
    const float* p_re   = (const float*)d_in[2];
    const float* p_im   = (const float*)d_in[3];
    const float* B_re   = (const float*)d_in[4];
    const float* B_im   = (const float*)d_in[5];
    const float* C_re   = (const float*)d_in[6];
    const float* C_im   = (const float*)d_in[7];
    const float* log_dt = (const float*)d_in[8];

    int dev = 0, sms = 148;
    cudaGetDevice(&dev);
    cudaDeviceGetAttribute(&sms, cudaDevAttrMultiProcessorCount, dev);

    cauchy_kernel<<<2 * sms, 256>>>(w_re, w_im, p_re, p_im,
                                    B_re, B_im, C_re, C_im, log_dt);

    ifft_kernel<<<HH, 512, 4608 * sizeof(float2)>>>((float*)d_out);
}

// round 11
// speedup vs baseline: 1.2332x; 1.2332x over previous
#include <cuda_runtime.h>
#include <math.h>

#define HH 256
#define NP 32
#define LL 8192
#define LH 4097           // L/2 + 1
#define M2 4096           // L/2  (packed real-IFFT size)
#define ROW 4098          // padded k_f row stride (keeps rows 16B-aligned)

#ifndef PI_D
#define PI_D 3.14159265358979323846
#endif

// scratch: k_f spectrum, one padded row per head (complex)
__device__ float2 g_kf[HH * ROW];

__device__ __forceinline__ float frcp(float x) {
    float r; asm("rcp.approx.f32 %0,%1;" : "=f"(r) : "f"(x)); return r;
}

// y = 2*tan(pi*l/L); double path near the Nyquist pole where float arg error
// is amplified by 1/(pi/2 - x).
__device__ __forceinline__ float y_of(int l) {
    if (l < 3968) return 2.0f * tanf((float)l * (float)(PI_D / (double)LL));
    return (float)(2.0 * tan((PI_D / (double)LL) * (double)l));
}

// Woodbury epilogue: k_f = (r00 - r01*r10/(1+r11)) * (1 + i*y/2)
__device__ __forceinline__ float2 woodbury(
    float r00r, float r00i, float r01r, float r01i,
    float r10r, float r10i, float r11r, float r11i, float y)
{
    const float drw = 1.f + r11r, diw = r11i;
    const float invd = frcp(fmaf(drw, drw, diw * diw));
    const float numr = r01r * r10r - r01i * r10i;
    const float numi = r01r * r10i + r01i * r10r;
    const float cr = (numr * drw + numi * diw) * invd;
    const float ci = (numi * drw - numr * diw) * invd;
    const float ar = r00r - cr, ai = r00i - ci;
    const float g = 0.5f * y;
    return make_float2(fmaf(-ai, g, ar), fmaf(ar, g, ai));
}

// ---------------------------------------------------------------------------
// Tail node l = 4096 (y ~ 3.3e16: d1*d2 would overflow the 2-basis path).
// Old safe per-pole formulation, one thread per head, reads gmem directly.
// ---------------------------------------------------------------------------
__device__ void cauchy_tail(
    const float* w_re, const float* w_im,
    const float* p_re, const float* p_im,
    const float* B_re, const float* B_im,
    const float* C_re, const float* C_im,
    const float* log_dt, int h, float2* row)
{
    const float y = y_of(4096);
    const float dt = expf(log_dt[h]);
    float r00r = 0, r00i = 0, r01r = 0, r01i = 0;
    float r10r = 0, r10i = 0, r11r = 0, r11i = 0;
    for (int n = 0; n < NP; n++) {
        const int idx = h * NP + n;
        const float a = w_re[idx] * dt, b = w_im[idx] * dt;
        const float Br = B_re[idx], Bi = B_im[idx];
        const float Pr = p_re[idx], Pi = p_im[idx];
        const float Cr = C_re[idx], Ci = C_im[idx];
        const float v00r = (Br * Cr - Bi * Ci) * dt, v00i = (Br * Ci + Bi * Cr) * dt;
        const float v01r = (Br * Pr + Bi * Pi) * dt, v01i = (Bi * Pr - Br * Pi) * dt;
        const float v10r = (Pr * Cr - Pi * Ci) * dt, v10i = (Pr * Ci + Pi * Cr) * dt;
        const float v11  = (Pr * Pr + Pi * Pi) * dt;
        const float t1 = y - b, t2 = y + b;
        const float d1 = fmaf(t1, t1, a * a), d2 = fmaf(t2, t2, a * a);
        const float inv1 = frcp(d1), inv2 = frcp(d2);
        const float u1 = t1 * inv1, u2 = t2 * inv2;
        const float Pinv = inv1 + inv2, Minv = inv2 - inv1;
        const float Pu = u1 + u2, Mu = u1 - u2;
        r00r += (-a * v00r) * Pinv + v00i * Mu;
        r00i += (-v00r) * Pu + (a * v00i) * Minv;
        r01r += (-a * v01r) * Pinv + v01i * Mu;
        r01i += (-v01r) * Pu + (a * v01i) * Minv;
        r10r += (-a * v10r) * Pinv + v10i * Mu;
        r10i += (-v10r) * Pu + (a * v10i) * Minv;
        r11r += (-a * v11) * Pinv;
        r11i += (-v11) * Pu;
    }
    row[4096] = woodbury(r00r, r00i, r01r, r01i, r10r, r10i, r11r, r11i, y);
}

// ---------------------------------------------------------------------------
// Kernel A: Cauchy sums + Woodbury -> k_f[h][l], 2-basis formulation.
// Per (pole,freq): t1,t2,d1,d2, II=rcp(d1*d2), SI=s*II (6 fma-ops + 1 MUFU),
// then 16 accumulate FMAs over bases (SI, II). Imag accumulators are
// multiplied by y once per freq in the epilogue.
// grid = (4, H), block = 256; each thread: pairs g and g+1024 (4 freqs).
// ---------------------------------------------------------------------------
__global__ __launch_bounds__(256) void cauchy_kernel(
    const float* __restrict__ w_re, const float* __restrict__ w_im,
    const float* __restrict__ p_re, const float* __restrict__ p_im,
    const float* __restrict__ B_re, const float* __restrict__ B_im,
    const float* __restrict__ C_re, const float* __restrict__ C_im,
    const float* __restrict__ log_dt)
{
    __shared__ float2 shb[NP];        // (b, a^2)
    __shared__ float4 shq[NP][4];     // (Gr, Hr, Gi, Hi) per output 00,01,10,11

    const int h   = blockIdx.y;
    const int tid = threadIdx.x;

    if (tid < NP) {
        const float dt = expf(log_dt[h]);
        const int idx = h * NP + tid;
        const float a  = w_re[idx] * dt;
        const float b  = w_im[idx] * dt;
        const float a2 = a * a, b2 = b * b;
        const float cab = a2 + b2, camb = a2 - b2, ab2 = 2.f * a * b;
        const float Br = B_re[idx], Bi = B_im[idx];
        const float Pr = p_re[idx], Pi = p_im[idx];
        const float Cr = C_re[idx], Ci = C_im[idx];
        const float v00r = (Br * Cr - Bi * Ci) * dt, v00i = (Br * Ci + Bi * Cr) * dt;
        const float v01r = (Br * Pr + Bi * Pi) * dt, v01i = (Bi * Pr - Br * Pi) * dt;
        const float v10r = (Pr * Cr - Pi * Ci) * dt, v10i = (Pr * Ci + Pi * Cr) * dt;
        const float v11  = (Pr * Pr + Pi * Pi) * dt;
        shb[tid] = make_float2(b, a2);
        // Gr = 2(b*vi - a*vr); Hr = -2*cab*(a*vr + b*vi)
        // Gi = -2*vr;          Hi = -2*(camb*vr + 2ab*vi)   [imag gets *y later]
        shq[tid][0] = make_float4(2.f * (b * v00i - a * v00r),
                                  -2.f * cab * (a * v00r + b * v00i),
                                  -2.f * v00r,
                                  -2.f * (camb * v00r + ab2 * v00i));
        shq[tid][1] = make_float4(2.f * (b * v01i - a * v01r),
                                  -2.f * cab * (a * v01r + b * v01i),
                                  -2.f * v01r,
                                  -2.f * (camb * v01r + ab2 * v01i));
        shq[tid][2] = make_float4(2.f * (b * v10i - a * v10r),
                                  -2.f * cab * (a * v10r + b * v10i),
                                  -2.f * v10r,
                                  -2.f * (camb * v10r + ab2 * v10i));
        shq[tid][3] = make_float4(-2.f * a * v11,
                                  -2.f * cab * a * v11,
                                  -2.f * v11,
                                  -2.f * camb * v11);
    }
    __syncthreads();

    const int g = blockIdx.x * 256 + tid;     // 0..1023
    const int pv[2] = { g, g + 1024 };        // pairs 0..2047 (l <= 4095)

    float y[4], s[4];
#pragma unroll
    for (int j = 0; j < 2; j++) {
        y[2 * j]     = y_of(2 * pv[j]);
        y[2 * j + 1] = y_of(2 * pv[j] + 1);
    }
#pragma unroll
    for (int f = 0; f < 4; f++) s[f] = y[f] * y[f];

    float Tr00[4], Ti00[4], Tr01[4], Ti01[4];
    float Tr10[4], Ti10[4], Tr11[4], Ti11[4];
#pragma unroll
    for (int f = 0; f < 4; f++) {
        Tr00[f] = Ti00[f] = Tr01[f] = Ti01[f] = 0.f;
        Tr10[f] = Ti10[f] = Tr11[f] = Ti11[f] = 0.f;
    }

#pragma unroll 2
    for (int n = 0; n < NP; n++) {
        const float2 ba = shb[n];
        const float4 q0 = shq[n][0];
        const float4 q1 = shq[n][1];
        const float4 q2 = shq[n][2];
        const float4 q3 = shq[n][3];

#pragma unroll
        for (int f = 0; f < 4; f++) {
            const float t1 = y[f] - ba.x;
            const float t2 = y[f] + ba.x;
            const float d1 = fmaf(t1, t1, ba.y);
            const float d2 = fmaf(t2, t2, ba.y);
            const float II = frcp(d1 * d2);
            const float SI = s[f] * II;

            Tr00[f] = fmaf(q0.x, SI, fmaf(q0.y, II, Tr00[f]));
            Ti00[f] = fmaf(q0.z, SI, fmaf(q0.w, II, Ti00[f]));
            Tr01[f] = fmaf(q1.x, SI, fmaf(q1.y, II, Tr01[f]));
            Ti01[f] = fmaf(q1.z, SI, fmaf(q1.w, II, Ti01[f]));
            Tr10[f] = fmaf(q2.x, SI, fmaf(q2.y, II, Tr10[f]));
            Ti10[f] = fmaf(q2.z, SI, fmaf(q2.w, II, Ti10[f]));
            Tr11[f] = fmaf(q3.x, SI, fmaf(q3.y, II, Tr11[f]));
            Ti11[f] = fmaf(q3.z, SI, fmaf(q3.w, II, Ti11[f]));
        }
    }

    float2* row = g_kf + h * ROW;
#pragma unroll
    for (int j = 0; j < 2; j++) {
        float2 res[2];
#pragma unroll
        for (int ss = 0; ss < 2; ss++) {
            const int f = 2 * j + ss;
            res[ss] = woodbury(Tr00[f], y[f] * Ti00[f],
                               Tr01[f], y[f] * Ti01[f],
                               Tr10[f], y[f] * Ti10[f],
                               Tr11[f], y[f] * Ti11[f], y[f]);
        }
        *reinterpret_cast<float4*>(row + 2 * pv[j]) =
            make_float4(res[0].x, res[0].y, res[1].x, res[1].y);
    }

    if (blockIdx.x == 0 && tid == 0) {
        cauchy_tail(w_re, w_im, p_re, p_im, B_re, B_im, C_re, C_im,
                    log_dt, h, row);
    }
}

// ---------------------------------------------------------------------------
// FFT helpers
// ---------------------------------------------------------------------------
__device__ __forceinline__ float2 cmul(float2 a, float2 b) {
    return make_float2(a.x * b.x - a.y * b.y, a.x * b.y + a.y * b.x);
}
__device__ __forceinline__ float2 cadd(float2 a, float2 b) {
    return make_float2(a.x + b.x, a.y + b.y);
}
__device__ __forceinline__ float2 csub(float2 a, float2 b) {
    return make_float2(a.x - b.x, a.y - b.y);
}
__device__ __forceinline__ float2 cmuli(float2 a) {     // i*a
    return make_float2(-a.y, a.x);
}
__device__ __forceinline__ int rev8(int k) {  // base-8 digit reversal, 12-bit
    return ((k & 7) << 9) | (((k >> 3) & 7) << 6) | (((k >> 6) & 7) << 3) | ((k >> 9) & 7);
}
#define PAD(i) ((i) + ((i) >> 3))             // smem skew: 4096 -> 4608 slots

// ---------------------------------------------------------------------------
// Kernel B: irfft(k_f), ONE head per 512-thread block, radix-8 DIT
// (4 stages, 3 barriers), last stage writes gmem from registers.
// grid = 256, block = 512, 36 KB dynamic shared (under 48 KB default).
// ---------------------------------------------------------------------------
__global__ __launch_bounds__(512) void ifft_kernel(float* __restrict__ out)
{
    extern __shared__ float2 spec[];          // 4608 float2 (36 KB)

    const int stid = threadIdx.x;             // 0..511
    const int h    = blockIdx.x;

    // Hermitian pack with 1/M scale folded in, base-8 digit-reversed layout.
    const float sc = 0.5f / (float)M2;
    const float2* kf = g_kf + h * ROW;
    for (int k = stid; k <= M2 / 2; k += 512) {
        const float2 Xk = kf[k];
        const float2 Xm = kf[M2 - k];
        const float mr = Xm.x, mi = -Xm.y;            // conj(X[M-k])
        const float Er = sc * (Xk.x + mr);
        const float Ei = sc * (Xk.y + mi);
        const float Fr = sc * (Xk.x - mr);
        const float Fi = sc * (Xk.y - mi);
        float s, c;
        __sincosf((float)k * (float)(PI_D / (double)M2), &s, &c); // e^{+i*pi*k/M}
        const float Or = c * Fr - s * Fi;
        const float Oi = c * Fi + s * Fr;
        spec[PAD(rev8(k))] = make_float2(Er - Oi, Ei + Or);
        if (k > 0 && k < M2 / 2) {
            spec[PAD(rev8(M2 - k))] = make_float2(Er + Oi, Or - Ei);
        }
    }
    __syncthreads();

    const float C8 = 0.70710678118654752f;    // sqrt(2)/2
    float2* outv = (float2*)out + h * M2;

    // 4 radix-8 stages: q = 1, 8, 64, 512. 512 butterflies/stage, 1/thread.
#pragma unroll 1
    for (int st = 0; st < 4; st++) {
        const int lq = 3 * st;                // log8 shift
        const int q  = 1 << lq;
        const int j  = stid;
        const int pos = j & (q - 1);
        const int i0  = ((j >> lq) << (lq + 3)) | pos;

        float2 v[8];
#pragma unroll
        for (int m = 0; m < 8; m++) v[m] = spec[PAD(i0 + m * q)];

        if (st > 0) {
            // external twiddles: v[m] *= e^{+2*pi*i*m*pos/(8q)}
            float s1, c1;
            __sincosf((float)pos * (float)(2.0 * PI_D / (8.0 * (double)q)), &s1, &c1);
            const float2 w1 = make_float2(c1, s1);
            const float2 w2 = cmul(w1, w1);
            const float2 w3 = cmul(w2, w1);
            const float2 w4 = cmul(w2, w2);
            const float2 w5 = cmul(w2, w3);
            const float2 w6 = cmul(w3, w3);
            const float2 w7 = cmul(w3, w4);
            v[1] = cmul(v[1], w1); v[2] = cmul(v[2], w2); v[3] = cmul(v[3], w3);
            v[4] = cmul(v[4], w4); v[5] = cmul(v[5], w5); v[6] = cmul(v[6], w6);
            v[7] = cmul(v[7], w7);
        }

        // inverse DFT8: even DFT4 (v0,v2,v4,v6), odd DFT4 (v1,v3,v5,v7), combine
        const float2 es = cadd(v[0], v[4]), ed = csub(v[0], v[4]);
        const float2 fs = cadd(v[2], v[6]), fd = csub(v[2], v[6]);
        const float2 E0 = cadd(es, fs);
        const float2 E1 = cadd(ed, cmuli(fd));
        const float2 E2 = csub(es, fs);
        const float2 E3 = csub(ed, cmuli(fd));

        const float2 os = cadd(v[1], v[5]), od = csub(v[1], v[5]);
        const float2 ps = cadd(v[3], v[7]), pd = csub(v[3], v[7]);
        const float2 O0 = cadd(os, ps);
        const float2 O1 = cadd(od, cmuli(pd));
        const float2 O2 = csub(os, ps);
        const float2 O3 = csub(od, cmuli(pd));

        // W8^m * O[m]:  W8^1=c(1+i), W8^2=i, W8^3=c(-1+i)
        const float2 T1 = make_float2(C8 * (O1.x - O1.y), C8 * (O1.x + O1.y));
        const float2 T2 = cmuli(O2);
        const float2 T3 = make_float2(C8 * (-O3.x - O3.y), C8 * (O3.x - O3.y));

        float2 X[8];
        X[0] = cadd(E0, O0);  X[4] = csub(E0, O0);
        X[1] = cadd(E1, T1);  X[5] = csub(E1, T1);
        X[2] = cadd(E2, T2);  X[6] = csub(E2, T2);
        X[3] = cadd(E3, T3);  X[7] = csub(E3, T3);

        if (st < 3) {
#pragma unroll
            for (int m = 0; m < 8; m++) spec[PAD(i0 + m * q)] = X[m];
            __syncthreads();
        } else {
            // q = 512, i0 = j: z[t] = x[2t] + i*x[2t+1], already scaled.
#pragma unroll
            for (int m = 0; m < 8; m++) outv[i0 + m * 512] = X[m];
        }
    }
}

// ---------------------------------------------------------------------------
extern "C" void kernel_launch(void* const* d_in, const int* in_sizes, int n_in,
                              void* d_out, int out_size)
{
    const float* w_re   = (const float*)d_in[0];
    const float* w_im   = (const float*)d_in[1];
    const float* p_re   = (const float*)d_in[2];
    const float* p_im   = (const float*)d_in[3];
    const float* B_re   = (const float*)d_in[4];
    const float* B_im   = (const float*)d_in[5];
    const float* C_re   = (const float*)d_in[6];
    const float* C_im   = (const float*)d_in[7];
    const float* log_dt = (const float*)d_in[8];

    dim3 gridA(4, HH);      // 4 blocks x 256 threads x 2 pairs per head
    cauchy_kernel<<<gridA, 256>>>(w_re, w_im, p_re, p_im,
                                  B_re, B_im, C_re, C_im, log_dt);

    ifft_kernel<<<HH, 512, 4608 * sizeof(float2)>>>((float*)d_out);
}

// round 12
// speedup vs baseline: 1.3220x; 1.0720x over previous
#include <cuda_runtime.h>
#include <math.h>

#define HH 256
#define NP 32
#define LL 8192
#define LH 4097           // L/2 + 1
#define M2 4096           // L/2  (packed real-IFFT size)
#define ROW 4098          // padded k_f row stride (keeps rows 16B-aligned)

#ifndef PI_D
#define PI_D 3.14159265358979323846
#endif

// scratch: k_f spectrum, one padded row per head (complex)
__device__ float2 g_kf[HH * ROW];

__device__ __forceinline__ float frcp(float x) {
    float r; asm("rcp.approx.f32 %0,%1;" : "=f"(r) : "f"(x)); return r;
}

// y = 2*tan(pi*l/L); double path near the Nyquist pole where float arg error
// is amplified by 1/(pi/2 - x).
__device__ __forceinline__ float y_of(int l) {
    if (l < 3968) return 2.0f * tanf((float)l * (float)(PI_D / (double)LL));
    return (float)(2.0 * tan((PI_D / (double)LL) * (double)l));
}

// Woodbury epilogue: k_f = (r00 - r01*r10/(1+r11)) * (1 + i*y/2)
__device__ __forceinline__ float2 woodbury(
    float r00r, float r00i, float r01r, float r01i,
    float r10r, float r10i, float r11r, float r11i, float y)
{
    const float drw = 1.f + r11r, diw = r11i;
    const float invd = frcp(fmaf(drw, drw, diw * diw));
    const float numr = r01r * r10r - r01i * r10i;
    const float numi = r01r * r10i + r01i * r10r;
    const float cr = (numr * drw + numi * diw) * invd;
    const float ci = (numi * drw - numr * diw) * invd;
    const float ar = r00r - cr, ai = r00i - ci;
    const float g = 0.5f * y;
    return make_float2(fmaf(-ai, g, ar), fmaf(ar, g, ai));
}

// ---------------------------------------------------------------------------
// Tail node l = 4096 (y ~ 3.3e16: T^2 would overflow the 2-basis path).
// Safe per-pole formulation, one thread per head, reads gmem directly.
// ---------------------------------------------------------------------------
__device__ void cauchy_tail(
    const float* w_re, const float* w_im,
    const float* p_re, const float* p_im,
    const float* B_re, const float* B_im,
    const float* C_re, const float* C_im,
    const float* log_dt, int h, float2* row)
{
    const float y = y_of(4096);
    const float dt = expf(log_dt[h]);
    float r00r = 0, r00i = 0, r01r = 0, r01i = 0;
    float r10r = 0, r10i = 0, r11r = 0, r11i = 0;
    for (int n = 0; n < NP; n++) {
        const int idx = h * NP + n;
        const float a = w_re[idx] * dt, b = w_im[idx] * dt;
        const float Br = B_re[idx], Bi = B_im[idx];
        const float Pr = p_re[idx], Pi = p_im[idx];
        const float Cr = C_re[idx], Ci = C_im[idx];
        const float v00r = (Br * Cr - Bi * Ci) * dt, v00i = (Br * Ci + Bi * Cr) * dt;
        const float v01r = (Br * Pr + Bi * Pi) * dt, v01i = (Bi * Pr - Br * Pi) * dt;
        const float v10r = (Pr * Cr - Pi * Ci) * dt, v10i = (Pr * Ci + Pi * Cr) * dt;
        const float v11  = (Pr * Pr + Pi * Pi) * dt;
        const float t1 = y - b, t2 = y + b;
        const float d1 = fmaf(t1, t1, a * a), d2 = fmaf(t2, t2, a * a);
        const float inv1 = frcp(d1), inv2 = frcp(d2);
        const float u1 = t1 * inv1, u2 = t2 * inv2;
        const float Pinv = inv1 + inv2, Minv = inv2 - inv1;
        const float Pu = u1 + u2, Mu = u1 - u2;
        r00r += (-a * v00r) * Pinv + v00i * Mu;
        r00i += (-v00r) * Pu + (a * v00i) * Minv;
        r01r += (-a * v01r) * Pinv + v01i * Mu;
        r01i += (-v01r) * Pu + (a * v01i) * Minv;
        r10r += (-a * v10r) * Pinv + v10i * Mu;
        r10i += (-v10r) * Pu + (a * v10i) * Minv;
        r11r += (-a * v11) * Pinv;
        r11i += (-v11) * Pu;
    }
    row[4096] = woodbury(r00r, r00i, r01r, r01i, r10r, r10i, r11r, r11i, y);
}

// ---------------------------------------------------------------------------
// Kernel A: Cauchy sums + Woodbury -> k_f[h][l].
// Cancellation-free 2-basis form. Per (pole,freq), with s = y^2, T = s - b^2:
//   D  = T^2 + 2a^2*s + (a^4 + 2a^2 b^2)        (all-positive, 1 add + 2 fma)
//   II = rcp(D)
//   re += (Gr*T + Hr)*II ; im += (Gi*T + Hi)*II (im scaled by y in epilogue)
// 19 fma-pipe ops + 1 MUFU per (pole,freq).
// grid = (4, H), block = 256; each thread: pairs g and g+1024 (4 freqs).
// ---------------------------------------------------------------------------
__global__ __launch_bounds__(256) void cauchy_kernel(
    const float* __restrict__ w_re, const float* __restrict__ w_im,
    const float* __restrict__ p_re, const float* __restrict__ p_im,
    const float* __restrict__ B_re, const float* __restrict__ B_im,
    const float* __restrict__ C_re, const float* __restrict__ C_im,
    const float* __restrict__ log_dt)
{
    __shared__ float4 shd[NP][5];

    const int h   = blockIdx.y;
    const int tid = threadIdx.x;

    if (tid < NP) {
        const float dt = expf(log_dt[h]);
        const int idx = h * NP + tid;
        const float a  = w_re[idx] * dt;
        const float b  = w_im[idx] * dt;
        const float a2 = a * a, b2 = b * b;
        const float Br = B_re[idx], Bi = B_im[idx];
        const float Pr = p_re[idx], Pi = p_im[idx];
        const float Cr = C_re[idx], Ci = C_im[idx];
        const float v00r = (Br * Cr - Bi * Ci) * dt, v00i = (Br * Ci + Bi * Cr) * dt;
        const float v01r = (Br * Pr + Bi * Pi) * dt, v01i = (Bi * Pr - Br * Pi) * dt;
        const float v10r = (Pr * Cr - Pi * Ci) * dt, v10i = (Pr * Ci + Pi * Cr) * dt;
        const float v11  = (Pr * Pr + Pi * Pi) * dt;
        // Gr = 2(b*vi - a*vr); Hr = -2a^2 b*vi - 2a(a^2+2b^2)*vr
        // Gi = -2vr;           Hi = -2a^2*vr - 4ab*vi        [imag *y later]
        const float ha = -2.f * a * (a2 + 2.f * b2);
        const float hb = -2.f * a2 * b;
        const float hc = -2.f * a2;
        const float hd = -4.f * a * b;
        shd[tid][0] = make_float4(b2, 2.f * a2, a2 * a2 + 2.f * a2 * b2,
                                  2.f * (b * v00i - a * v00r));
        shd[tid][1] = make_float4(hb * v00i + ha * v00r,
                                  -2.f * v00r,
                                  hc * v00r + hd * v00i,
                                  2.f * (b * v01i - a * v01r));
        shd[tid][2] = make_float4(hb * v01i + ha * v01r,
                                  -2.f * v01r,
                                  hc * v01r + hd * v01i,
                                  2.f * (b * v10i - a * v10r));
        shd[tid][3] = make_float4(hb * v10i + ha * v10r,
                                  -2.f * v10r,
                                  hc * v10r + hd * v10i,
                                  -2.f * a * v11);
        shd[tid][4] = make_float4(ha * v11,
                                  -2.f * v11,
                                  hc * v11,
                                  0.f);
    }
    __syncthreads();

    const int g = blockIdx.x * 256 + tid;     // 0..1023
    const int pv[2] = { g, g + 1024 };        // pairs 0..2047 (l <= 4095)

    float y[4], s[4];
#pragma unroll
    for (int j = 0; j < 2; j++) {
        y[2 * j]     = y_of(2 * pv[j]);
        y[2 * j + 1] = y_of(2 * pv[j] + 1);
    }
#pragma unroll
    for (int f = 0; f < 4; f++) s[f] = y[f] * y[f];

    float Tr00[4], Ti00[4], Tr01[4], Ti01[4];
    float Tr10[4], Ti10[4], Tr11[4], Ti11[4];
#pragma unroll
    for (int f = 0; f < 4; f++) {
        Tr00[f] = Ti00[f] = Tr01[f] = Ti01[f] = 0.f;
        Tr10[f] = Ti10[f] = Tr11[f] = Ti11[f] = 0.f;
    }

#pragma unroll 2
    for (int n = 0; n < NP; n++) {
        const float4 d0 = shd[n][0];   // b2, 2a2, K1, Gr00
        const float4 d1 = shd[n][1];   // Hr00, Gi00, Hi00, Gr01
        const float4 d2 = shd[n][2];   // Hr01, Gi01, Hi01, Gr10
        const float4 d3 = shd[n][3];   // Hr10, Gi10, Hi10, Gr11
        const float4 d4 = shd[n][4];   // Hr11, Gi11, Hi11, -

#pragma unroll
        for (int f = 0; f < 4; f++) {
            const float T  = s[f] - d0.x;                      // y^2 - b^2
            const float D  = fmaf(T, T, fmaf(d0.y, s[f], d0.z));
            const float II = frcp(D);

            Tr00[f] = fmaf(fmaf(d0.w, T, d1.x), II, Tr00[f]);
            Ti00[f] = fmaf(fmaf(d1.y, T, d1.z), II, Ti00[f]);
            Tr01[f] = fmaf(fmaf(d1.w, T, d2.x), II, Tr01[f]);
            Ti01[f] = fmaf(fmaf(d2.y, T, d2.z), II, Ti01[f]);
            Tr10[f] = fmaf(fmaf(d2.w, T, d3.x), II, Tr10[f]);
            Ti10[f] = fmaf(fmaf(d3.y, T, d3.z), II, Ti10[f]);
            Tr11[f] = fmaf(fmaf(d3.w, T, d4.x), II, Tr11[f]);
            Ti11[f] = fmaf(fmaf(d4.y, T, d4.z), II, Ti11[f]);
        }
    }

    float2* row = g_kf + h * ROW;
#pragma unroll
    for (int j = 0; j < 2; j++) {
        float2 res[2];
#pragma unroll
        for (int ss = 0; ss < 2; ss++) {
            const int f = 2 * j + ss;
            res[ss] = woodbury(Tr00[f], y[f] * Ti00[f],
                               Tr01[f], y[f] * Ti01[f],
                               Tr10[f], y[f] * Ti10[f],
                               Tr11[f], y[f] * Ti11[f], y[f]);
        }
        *reinterpret_cast<float4*>(row + 2 * pv[j]) =
            make_float4(res[0].x, res[0].y, res[1].x, res[1].y);
    }

    if (blockIdx.x == 0 && tid == 0) {
        cauchy_tail(w_re, w_im, p_re, p_im, B_re, B_im, C_re, C_im,
                    log_dt, h, row);
    }
}

// ---------------------------------------------------------------------------
// FFT helpers
// ---------------------------------------------------------------------------
__device__ __forceinline__ float2 cmul(float2 a, float2 b) {
    return make_float2(a.x * b.x - a.y * b.y, a.x * b.y + a.y * b.x);
}
__device__ __forceinline__ float2 cadd(float2 a, float2 b) {
    return make_float2(a.x + b.x, a.y + b.y);
}
__device__ __forceinline__ float2 csub(float2 a, float2 b) {
    return make_float2(a.x - b.x, a.y - b.y);
}
__device__ __forceinline__ float2 cmuli(float2 a) {     // i*a
    return make_float2(-a.y, a.x);
}
__device__ __forceinline__ int rev8(int k) {  // base-8 digit reversal, 12-bit
    return ((k & 7) << 9) | (((k >> 3) & 7) << 6) | (((k >> 6) & 7) << 3) | ((k >> 9) & 7);
}
#define PAD(i) ((i) + ((i) >> 3))             // smem skew: 4096 -> 4608 slots

// ---------------------------------------------------------------------------
// Kernel B: irfft(k_f), ONE head per 512-thread block, radix-8 DIT
// (4 stages, 3 barriers), last stage writes gmem from registers.
// grid = 256, block = 512, 36 KB dynamic shared (under 48 KB default).
// ---------------------------------------------------------------------------
__global__ __launch_bounds__(512) void ifft_kernel(float* __restrict__ out)
{
    extern __shared__ float2 spec[];          // 4608 float2 (36 KB)

    const int stid = threadIdx.x;             // 0..511
    const int h    = blockIdx.x;

    // Hermitian pack with 1/M scale folded in, base-8 digit-reversed layout.
    const float sc = 0.5f / (float)M2;
    const float2* kf = g_kf + h * ROW;
    for (int k = stid; k <= M2 / 2; k += 512) {
        const float2 Xk = kf[k];
        const float2 Xm = kf[M2 - k];
        const float mr = Xm.x, mi = -Xm.y;            // conj(X[M-k])
        const float Er = sc * (Xk.x + mr);
        const float Ei = sc * (Xk.y + mi);
        const float Fr = sc * (Xk.x - mr);
        const float Fi = sc * (Xk.y - mi);
        float s, c;
        __sincosf((float)k * (float)(PI_D / (double)M2), &s, &c); // e^{+i*pi*k/M}
        const float Or = c * Fr - s * Fi;
        const float Oi = c * Fi + s * Fr;
        spec[PAD(rev8(k))] = make_float2(Er - Oi, Ei + Or);
        if (k > 0 && k < M2 / 2) {
            spec[PAD(rev8(M2 - k))] = make_float2(Er + Oi, Or - Ei);
        }
    }
    __syncthreads();

    const float C8 = 0.70710678118654752f;    // sqrt(2)/2
    float2* outv = (float2*)out + h * M2;

    // 4 radix-8 stages: q = 1, 8, 64, 512. 512 butterflies/stage, 1/thread.
#pragma unroll 1
    for (int st = 0; st < 4; st++) {
        const int lq = 3 * st;                // log8 shift
        const int q  = 1 << lq;
        const int j  = stid;
        const int pos = j & (q - 1);
        const int i0  = ((j >> lq) << (lq + 3)) | pos;

        float2 v[8];
#pragma unroll
        for (int m = 0; m < 8; m++) v[m] = spec[PAD(i0 + m * q)];

        if (st > 0) {
            // external twiddles: v[m] *= e^{+2*pi*i*m*pos/(8q)}
            float s1, c1;
            __sincosf((float)pos * (float)(2.0 * PI_D / (8.0 * (double)q)), &s1, &c1);
            const float2 w1 = make_float2(c1, s1);
            const float2 w2 = cmul(w1, w1);
            const float2 w3 = cmul(w2, w1);
            const float2 w4 = cmul(w2, w2);
            const float2 w5 = cmul(w2, w3);
            const float2 w6 = cmul(w3, w3);
            const float2 w7 = cmul(w3, w4);
            v[1] = cmul(v[1], w1); v[2] = cmul(v[2], w2); v[3] = cmul(v[3], w3);
            v[4] = cmul(v[4], w4); v[5] = cmul(v[5], w5); v[6] = cmul(v[6], w6);
            v[7] = cmul(v[7], w7);
        }

        // inverse DFT8: even DFT4 (v0,v2,v4,v6), odd DFT4 (v1,v3,v5,v7), combine
        const float2 es = cadd(v[0], v[4]), ed = csub(v[0], v[4]);
        const float2 fs = cadd(v[2], v[6]), fd = csub(v[2], v[6]);
        const float2 E0 = cadd(es, fs);
        const float2 E1 = cadd(ed, cmuli(fd));
        const float2 E2 = csub(es, fs);
        const float2 E3 = csub(ed, cmuli(fd));

        const float2 os = cadd(v[1], v[5]), od = csub(v[1], v[5]);
        const float2 ps = cadd(v[3], v[7]), pd = csub(v[3], v[7]);
        const float2 O0 = cadd(os, ps);
        const float2 O1 = cadd(od, cmuli(pd));
        const float2 O2 = csub(os, ps);
        const float2 O3 = csub(od, cmuli(pd));

        // W8^m * O[m]:  W8^1=c(1+i), W8^2=i, W8^3=c(-1+i)
        const float2 T1 = make_float2(C8 * (O1.x - O1.y), C8 * (O1.x + O1.y));
        const float2 T2 = cmuli(O2);
        const float2 T3 = make_float2(C8 * (-O3.x - O3.y), C8 * (O3.x - O3.y));

        float2 X[8];
        X[0] = cadd(E0, O0);  X[4] = csub(E0, O0);
        X[1] = cadd(E1, T1);  X[5] = csub(E1, T1);
        X[2] = cadd(E2, T2);  X[6] = csub(E2, T2);
        X[3] = cadd(E3, T3);  X[7] = csub(E3, T3);

        if (st < 3) {
#pragma unroll
            for (int m = 0; m < 8; m++) spec[PAD(i0 + m * q)] = X[m];
            __syncthreads();
        } else {
            // q = 512, i0 = j: z[t] = x[2t] + i*x[2t+1], already scaled.
#pragma unroll
            for (int m = 0; m < 8; m++) outv[i0 + m * 512] = X[m];
        }
    }
}

// ---------------------------------------------------------------------------
extern "C" void kernel_launch(void* const* d_in, const int* in_sizes, int n_in,
                              void* d_out, int out_size)
{
    const float* w_re   = (const float*)d_in[0];
    const float* w_im   = (const float*)d_in[1];
    const float* p_re   = (const float*)d_in[2];
    const float* p_im   = (const float*)d_in[3];
    const float* B_re   = (const float*)d_in[4];
    const float* B_im   = (const float*)d_in[5];
    const float* C_re   = (const float*)d_in[6];
    const float* C_im   = (const float*)d_in[7];
    const float* log_dt = (const float*)d_in[8];

    dim3 gridA(4, HH);      // 4 blocks x 256 threads x 2 pairs per head
    cauchy_kernel<<<gridA, 256>>>(w_re, w_im, p_re, p_im,
                                  B_re, B_im, C_re, C_im, log_dt);

    ifft_kernel<<<HH, 512, 4608 * sizeof(float2)>>>((float*)d_out);
}